// round 3
// baseline (speedup 1.0000x reference)
#include <cuda_runtime.h>
#include <cuda_bf16.h>

#define NODES_CAP 100000
#define CH 64

// Scratch: aggregation buffer (init to x, then scatter-added).
__device__ float g_agg[(size_t)NODES_CAP * CH];
// Edge-index dtype flag: 1 if the buffer is int64, 0 if int32.
__device__ int g_ei_is64;

// ---------------------------------------------------------------------------
// Kernel 0: probe edge_index dtype. int64 values < 2^31 have zero high words
// at every odd 32-bit position; genuine int32 node IDs essentially never do.
// Deterministic, rerun every launch (graph-safe).
// ---------------------------------------------------------------------------
__global__ void probe_ei_kernel(const int* __restrict__ ei32) {
    int all_zero = 1;
    for (int i = 1; i < 64; i += 2)
        if (ei32[i] != 0) { all_zero = 0; break; }
    g_ei_is64 = all_zero;
}

// ---------------------------------------------------------------------------
// Kernel 1: agg = x   (vectorized copy; folds the "+x" of GIN eps=0 for free)
// ---------------------------------------------------------------------------
__global__ void init_agg_kernel(const float4* __restrict__ x, float4* __restrict__ agg,
                                int n4) {
    int i = blockIdx.x * blockDim.x + threadIdx.x;
    if (i < n4) agg[i] = x[i];
}

// ---------------------------------------------------------------------------
// Kernel 2: scatter-add. 16 threads per edge, 4 channels each (float4 read,
// 4 scalar atomicAdds -> RED.F32 at spread addresses, L2-resident).
// ---------------------------------------------------------------------------
__global__ void scatter_kernel(const float* __restrict__ x,
                               const void* __restrict__ ei_raw,
                               float* __restrict__ agg, int E, int n) {
    int t = blockIdx.x * blockDim.x + threadIdx.x;
    int e = t >> 4;
    if (e >= E) return;
    int sub = t & 15;

    int s, d;
    if (g_ei_is64) {
        const long long* ei = (const long long*)ei_raw;
        s = (int)ei[e];
        d = (int)ei[(size_t)E + e];
    } else {
        const int* ei = (const int*)ei_raw;
        s = ei[e];
        d = ei[(size_t)E + e];
    }
    if ((unsigned)s >= (unsigned)n || (unsigned)d >= (unsigned)n) return;

    float4 v = *(const float4*)(x + (size_t)s * CH + sub * 4);
    float* a = agg + (size_t)d * CH + sub * 4;
    atomicAdd(a + 0, v.x);
    atomicAdd(a + 1, v.y);
    atomicAdd(a + 2, v.z);
    atomicAdd(a + 3, v.w);
}

// ---------------------------------------------------------------------------
// Kernel 3: fused MLP. 128 rows per block, one row per thread.
// h row in registers; W transposed in smem so the k-loop is broadcast LDS.128.
// smem rows padded to 65 floats for conflict-free per-row scalar access.
// ---------------------------------------------------------------------------
#define MLP_ROWS 128
#define HS_PITCH 65

__global__ void __launch_bounds__(128, 1)
mlp_kernel(const float* __restrict__ h_in,
           const float* __restrict__ W1, const float* __restrict__ b1,
           const float* __restrict__ W2, const float* __restrict__ b2,
           const float* __restrict__ alpha,
           float* __restrict__ out, int n, int out_size) {
    extern __shared__ float sm[];
    float* W1t = sm;                 // [64][64] transposed: W1t[c*64+k] = W1[k*64+c]
    float* W2t = W1t + CH * CH;
    float* b1s = W2t + CH * CH;
    float* b2s = b1s + CH;
    float* hs  = b2s + CH;           // [128][65]

    const int tid = threadIdx.x;
    const int row0 = blockIdx.x * MLP_ROWS;

    // Load + transpose weights (once per block; gmem reads coalesced).
    for (int i = tid; i < CH * CH; i += 128) {
        int k = i >> 6, c = i & 63;
        W1t[c * CH + k] = W1[i];
        W2t[c * CH + k] = W2[i];
    }
    if (tid < CH) { b1s[tid] = b1[tid]; b2s[tid] = b2[tid]; }

    // Cooperative coalesced load of input rows into padded smem.
    {
        const float4* src = (const float4*)(h_in + (size_t)row0 * CH);
        int valid4 = (n - row0 < MLP_ROWS ? (n - row0 > 0 ? n - row0 : 0) : MLP_ROWS) * (CH / 4);
        for (int i = tid; i < MLP_ROWS * (CH / 4); i += 128) {
            float4 v = (i < valid4) ? src[i] : make_float4(0.f, 0.f, 0.f, 0.f);
            int r = i >> 4, q = (i & 15) * 4;
            float* dp = hs + r * HS_PITCH + q;
            dp[0] = v.x; dp[1] = v.y; dp[2] = v.z; dp[3] = v.w;
        }
    }
    __syncthreads();

    const float gate = 1.0f / (1.0f + __expf(-alpha[0]));

    // Each thread owns row `tid`: pull into registers (conflict-free: bank = tid+k).
    float h[CH];
    #pragma unroll
    for (int k = 0; k < CH; k++) h[k] = hs[tid * HS_PITCH + k];

    // Layer 1: relu(h @ W1 + b1) -> back into own smem row (no cross-thread hazard).
    for (int c = 0; c < CH; c++) {
        float a0 = 0.f, a1 = 0.f, a2 = 0.f, a3 = 0.f;
        const float4* w = (const float4*)(W1t + c * CH);
        #pragma unroll
        for (int k = 0; k < CH / 4; k++) {
            float4 wv = w[k];   // uniform address across warp -> broadcast
            a0 += h[4 * k + 0] * wv.x;
            a1 += h[4 * k + 1] * wv.y;
            a2 += h[4 * k + 2] * wv.z;
            a3 += h[4 * k + 3] * wv.w;
        }
        float r = (a0 + a1) + (a2 + a3) + b1s[c];
        hs[tid * HS_PITCH + c] = fmaxf(r, 0.f);
    }

    #pragma unroll
    for (int k = 0; k < CH; k++) h[k] = hs[tid * HS_PITCH + k];

    // Layer 2: gate * (h1 @ W2 + b2) -> own smem row.
    for (int c = 0; c < CH; c++) {
        float a0 = 0.f, a1 = 0.f, a2 = 0.f, a3 = 0.f;
        const float4* w = (const float4*)(W2t + c * CH);
        #pragma unroll
        for (int k = 0; k < CH / 4; k++) {
            float4 wv = w[k];
            a0 += h[4 * k + 0] * wv.x;
            a1 += h[4 * k + 1] * wv.y;
            a2 += h[4 * k + 2] * wv.z;
            a3 += h[4 * k + 3] * wv.w;
        }
        float r = (a0 + a1) + (a2 + a3) + b2s[c];
        hs[tid * HS_PITCH + c] = gate * r;
    }
    __syncthreads();

    // Cooperative coalesced store.
    {
        int validf = (n - row0 < MLP_ROWS ? (n - row0 > 0 ? n - row0 : 0) : MLP_ROWS) * CH;
        float* dst = out + (size_t)row0 * CH;
        for (int i = tid; i < MLP_ROWS * CH; i += 128) {
            if (i < validf) {
                int r = i >> 6, c = i & 63;
                dst[i] = hs[r * HS_PITCH + c];
            }
        }
    }

    // Tail element: the gate scalar (second output of the reference tuple).
    if (blockIdx.x == 0 && tid == 0 && out_size > n * CH) out[(size_t)n * CH] = gate;
}

// ---------------------------------------------------------------------------
extern "C" void kernel_launch(void* const* d_in, const int* in_sizes, int n_in,
                              void* d_out, int out_size) {
    const float* x     = (const float*)d_in[0];
    const void*  ei    = d_in[1];
    const float* W1    = (const float*)d_in[2];
    const float* b1    = (const float*)d_in[3];
    const float* W2    = (const float*)d_in[4];
    const float* b2    = (const float*)d_in[5];
    const float* alpha = (const float*)d_in[6];
    float* out = (float*)d_out;

    int n = in_sizes[0] / CH;            // nodes
    int E = in_sizes[1] / 2;             // edges (edge_index is [2, E])
    if (n > NODES_CAP) n = NODES_CAP;    // scratch capacity guard

    float* agg;
    cudaGetSymbolAddress((void**)&agg, g_agg);

    // 0) detect edge_index dtype (int32 vs int64)
    probe_ei_kernel<<<1, 1>>>((const int*)ei);

    // 1) agg = x
    int n4 = n * (CH / 4);
    init_agg_kernel<<<(n4 + 255) / 256, 256>>>((const float4*)x, (float4*)agg, n4);

    // 2) scatter-add neighbors
    long long thr = (long long)E * 16;
    int sblocks = (int)((thr + 255) / 256);
    scatter_kernel<<<sblocks, 256>>>(x, ei, agg, E, n);

    // 3) fused MLP + gate
    int smem = (2 * CH * CH + 2 * CH + MLP_ROWS * HS_PITCH) * sizeof(float);
    cudaFuncSetAttribute(mlp_kernel, cudaFuncAttributeMaxDynamicSharedMemorySize, smem);
    int mblocks = (n + MLP_ROWS - 1) / MLP_ROWS;
    mlp_kernel<<<mblocks, 128, smem>>>(agg, W1, b1, W2, b2, alpha, out, n, out_size);
}

// round 7
// speedup vs baseline: 1.7293x; 1.7293x over previous
#include <cuda_runtime.h>
#include <cuda_bf16.h>

#define NODES_CAP 100000
#define CH 64

// Scratch: aggregation buffer (init to x, then scatter-added).
__device__ float g_agg[(size_t)NODES_CAP * CH];
// Edge-index dtype flag: 1 if the buffer is int64, 0 if int32.
__device__ int g_ei_is64;

// ---------------------------------------------------------------------------
// Kernel 0: probe edge_index dtype (int64 values < 2^31 have zero odd words).
// ---------------------------------------------------------------------------
__global__ void probe_ei_kernel(const int* __restrict__ ei32) {
    int all_zero = 1;
    for (int i = 1; i < 64; i += 2)
        if (ei32[i] != 0) { all_zero = 0; break; }
    g_ei_is64 = all_zero;
}

// ---------------------------------------------------------------------------
// Kernel 1: agg = x (folds the "+x" of GIN eps=0 for free)
// ---------------------------------------------------------------------------
__global__ void init_agg_kernel(const float4* __restrict__ x, float4* __restrict__ agg,
                                int n4) {
    int i = blockIdx.x * blockDim.x + threadIdx.x;
    if (i < n4) agg[i] = x[i];
}

// ---------------------------------------------------------------------------
// Kernel 2: scatter-add. 4 threads per edge, each does 4x (LDG.128 + RED.v4).
// red.global.add.v4.f32 quarters the L2-atomic op count vs scalar atomicAdd.
// ---------------------------------------------------------------------------
__device__ __forceinline__ void red_add_v4(float* p, float4 v) {
    asm volatile("red.global.add.v4.f32 [%0], {%1, %2, %3, %4};"
                 :: "l"(p), "f"(v.x), "f"(v.y), "f"(v.z), "f"(v.w)
                 : "memory");
}

__global__ void scatter_kernel(const float* __restrict__ x,
                               const void* __restrict__ ei_raw,
                               float* __restrict__ agg, int E, int n) {
    int t = blockIdx.x * blockDim.x + threadIdx.x;
    int e = t >> 2;
    if (e >= E) return;
    int sub = t & 3;   // 16 channels each

    int s, d;
    if (g_ei_is64) {
        const long long* ei = (const long long*)ei_raw;
        s = (int)ei[e];
        d = (int)ei[(size_t)E + e];
    } else {
        const int* ei = (const int*)ei_raw;
        s = ei[e];
        d = ei[(size_t)E + e];
    }
    if ((unsigned)s >= (unsigned)n || (unsigned)d >= (unsigned)n) return;

    const float4* src = (const float4*)(x + (size_t)s * CH + sub * 16);
    float*        dst = agg + (size_t)d * CH + sub * 16;
    float4 v0 = src[0], v1 = src[1], v2 = src[2], v3 = src[3];
    red_add_v4(dst + 0,  v0);
    red_add_v4(dst + 4,  v1);
    red_add_v4(dst + 8,  v2);
    red_add_v4(dst + 12, v3);
}

// ---------------------------------------------------------------------------
// Kernel 3: fused MLP, register-tiled. Block = 128 threads, 128 rows.
// Thread (tx=tid&31, ty=tid>>5) computes rows {tx, tx+32, tx+64, tx+96} x
// cols [16*ty, 16*ty+16): 64 accumulators. Per k-step: 4 scalar h loads
// (conflict-free, pitch 65) + 4 broadcast float4 weight loads (row-major, no
// transpose) feeding 64 FFMAs -> LDS:FFMA = 1:8 (was 1:4 with all-broadcast).
// ---------------------------------------------------------------------------
#define MLP_ROWS 128
#define HP 65

__global__ void __launch_bounds__(128)
mlp_kernel(const float* __restrict__ h_in,
           const float* __restrict__ W1, const float* __restrict__ b1,
           const float* __restrict__ W2, const float* __restrict__ b2,
           const float* __restrict__ alpha,
           float* __restrict__ out, int n, int out_size) {
    extern __shared__ float sm[];
    float* W1s = sm;                  // [64][64] row-major (as stored)
    float* W2s = W1s + CH * CH;
    float* b1s = W2s + CH * CH;
    float* b2s = b1s + CH;
    float* hs  = b2s + CH;            // [128][65]

    const int tid = threadIdx.x;
    const int tx  = tid & 31;
    const int ty  = tid >> 5;
    const int c0  = ty * 16;
    const int row0 = blockIdx.x * MLP_ROWS;

    for (int i = tid; i < CH * CH; i += 128) { W1s[i] = W1[i]; W2s[i] = W2[i]; }
    if (tid < CH) { b1s[tid] = b1[tid]; b2s[tid] = b2[tid]; }

    // Coalesced load of 128 input rows into padded smem.
    {
        const float4* src = (const float4*)(h_in + (size_t)row0 * CH);
        int valid4 = (n - row0 < MLP_ROWS ? (n - row0 > 0 ? n - row0 : 0) : MLP_ROWS) * (CH / 4);
        for (int i = tid; i < MLP_ROWS * (CH / 4); i += 128) {
            float4 v = (i < valid4) ? src[i] : make_float4(0.f, 0.f, 0.f, 0.f);
            int r = i >> 4, q = (i & 15) * 4;
            float* dp = hs + r * HP + q;
            dp[0] = v.x; dp[1] = v.y; dp[2] = v.z; dp[3] = v.w;
        }
    }
    __syncthreads();

    const float gate = 1.0f / (1.0f + __expf(-alpha[0]));

    float acc[4][16];

    // ---- Layer 1: relu(h @ W1 + b1) ----
    #pragma unroll
    for (int j = 0; j < 4; j++)
        #pragma unroll
        for (int c = 0; c < 16; c++) acc[j][c] = b1s[c0 + c];

    #pragma unroll 4
    for (int k = 0; k < CH; k++) {
        float hv0 = hs[(tx +  0) * HP + k];
        float hv1 = hs[(tx + 32) * HP + k];
        float hv2 = hs[(tx + 64) * HP + k];
        float hv3 = hs[(tx + 96) * HP + k];
        const float4* wr = (const float4*)(W1s + k * CH + c0);
        float4 wa = wr[0], wb = wr[1], wc = wr[2], wd = wr[3];
        float w[16] = {wa.x, wa.y, wa.z, wa.w, wb.x, wb.y, wb.z, wb.w,
                       wc.x, wc.y, wc.z, wc.w, wd.x, wd.y, wd.z, wd.w};
        #pragma unroll
        for (int c = 0; c < 16; c++) {
            acc[0][c] += hv0 * w[c];
            acc[1][c] += hv1 * w[c];
            acc[2][c] += hv2 * w[c];
            acc[3][c] += hv3 * w[c];
        }
    }
    __syncthreads();   // everyone done reading hs
    #pragma unroll
    for (int j = 0; j < 4; j++)
        #pragma unroll
        for (int c = 0; c < 16; c++)
            hs[(32 * j + tx) * HP + c0 + c] = fmaxf(acc[j][c], 0.f);
    __syncthreads();

    // ---- Layer 2: gate * (h1 @ W2 + b2) ----
    #pragma unroll
    for (int j = 0; j < 4; j++)
        #pragma unroll
        for (int c = 0; c < 16; c++) acc[j][c] = b2s[c0 + c];

    #pragma unroll 4
    for (int k = 0; k < CH; k++) {
        float hv0 = hs[(tx +  0) * HP + k];
        float hv1 = hs[(tx + 32) * HP + k];
        float hv2 = hs[(tx + 64) * HP + k];
        float hv3 = hs[(tx + 96) * HP + k];
        const float4* wr = (const float4*)(W2s + k * CH + c0);
        float4 wa = wr[0], wb = wr[1], wc = wr[2], wd = wr[3];
        float w[16] = {wa.x, wa.y, wa.z, wa.w, wb.x, wb.y, wb.z, wb.w,
                       wc.x, wc.y, wc.z, wc.w, wd.x, wd.y, wd.z, wd.w};
        #pragma unroll
        for (int c = 0; c < 16; c++) {
            acc[0][c] += hv0 * w[c];
            acc[1][c] += hv1 * w[c];
            acc[2][c] += hv2 * w[c];
            acc[3][c] += hv3 * w[c];
        }
    }
    __syncthreads();
    #pragma unroll
    for (int j = 0; j < 4; j++)
        #pragma unroll
        for (int c = 0; c < 16; c++)
            hs[(32 * j + tx) * HP + c0 + c] = gate * acc[j][c];
    __syncthreads();

    // Coalesced store.
    {
        int validf = (n - row0 < MLP_ROWS ? (n - row0 > 0 ? n - row0 : 0) : MLP_ROWS) * CH;
        float* dst = out + (size_t)row0 * CH;
        for (int i = tid; i < MLP_ROWS * CH; i += 128) {
            if (i < validf) {
                int r = i >> 6, c = i & 63;
                dst[i] = hs[r * HP + c];
            }
        }
    }

    if (blockIdx.x == 0 && tid == 0 && out_size > n * CH) out[(size_t)n * CH] = gate;
}

// ---------------------------------------------------------------------------
extern "C" void kernel_launch(void* const* d_in, const int* in_sizes, int n_in,
                              void* d_out, int out_size) {
    const float* x     = (const float*)d_in[0];
    const void*  ei    = d_in[1];
    const float* W1    = (const float*)d_in[2];
    const float* b1    = (const float*)d_in[3];
    const float* W2    = (const float*)d_in[4];
    const float* b2    = (const float*)d_in[5];
    const float* alpha = (const float*)d_in[6];
    float* out = (float*)d_out;

    int n = in_sizes[0] / CH;
    int E = in_sizes[1] / 2;
    if (n > NODES_CAP) n = NODES_CAP;

    float* agg;
    cudaGetSymbolAddress((void**)&agg, g_agg);

    probe_ei_kernel<<<1, 1>>>((const int*)ei);

    int n4 = n * (CH / 4);
    init_agg_kernel<<<(n4 + 255) / 256, 256>>>((const float4*)x, (float4*)agg, n4);

    long long thr = (long long)E * 4;
    int sblocks = (int)((thr + 255) / 256);
    scatter_kernel<<<sblocks, 256>>>(x, ei, agg, E, n);

    int smem = (2 * CH * CH + 2 * CH + MLP_ROWS * HP) * sizeof(float);
    cudaFuncSetAttribute(mlp_kernel, cudaFuncAttributeMaxDynamicSharedMemorySize, smem);
    int mblocks = (n + MLP_ROWS - 1) / MLP_ROWS;
    mlp_kernel<<<mblocks, 128, smem>>>(agg, W1, b1, W2, b2, alpha, out, n, out_size);
}

// round 9
// speedup vs baseline: 1.7826x; 1.0308x over previous
#include <cuda_runtime.h>
#include <cuda_bf16.h>

#define NODES_CAP 100000
#define EDGES_CAP 1600000
#define CH 64

// Scratch
__device__ float g_agg[(size_t)NODES_CAP * CH];   // fallback path only
__device__ int g_counts[NODES_CAP];
__device__ int g_offsets[NODES_CAP];
__device__ int g_cursor[NODES_CAP];
__device__ int g_sorted_src[EDGES_CAP];
__device__ int g_partials[256];
__device__ int g_ei_is64;

// ---------------------------------------------------------------------------
// Probe edge_index dtype (int64 values < 2^31 have zero odd 32-bit words).
// ---------------------------------------------------------------------------
__global__ void probe_ei_kernel(const int* __restrict__ ei32) {
    int all_zero = 1;
    for (int i = 1; i < 64; i += 2)
        if (ei32[i] != 0) { all_zero = 0; break; }
    g_ei_is64 = all_zero;
}

__device__ __forceinline__ void load_edge(const void* ei_raw, int E, int e,
                                          int& s, int& d) {
    if (g_ei_is64) {
        const long long* ei = (const long long*)ei_raw;
        s = (int)ei[e];
        d = (int)ei[(size_t)E + e];
    } else {
        const int* ei = (const int*)ei_raw;
        s = ei[e];
        d = ei[(size_t)E + e];
    }
}

// ---------------------------------------------------------------------------
// Counting sort by destination
// ---------------------------------------------------------------------------
__global__ void zero_counts_kernel(int* __restrict__ counts, int n) {
    int i = blockIdx.x * blockDim.x + threadIdx.x;
    if (i < n) counts[i] = 0;
}

__global__ void hist_kernel(const void* __restrict__ ei_raw,
                            int* __restrict__ counts, int E, int n) {
    int e = blockIdx.x * blockDim.x + threadIdx.x;
    if (e >= E) return;
    int s, d; load_edge(ei_raw, E, e, s, d);
    if ((unsigned)s >= (unsigned)n || (unsigned)d >= (unsigned)n) return;
    atomicAdd(&counts[d], 1);
}

__global__ void scan1_kernel(const int* __restrict__ counts,
                             int* __restrict__ offsets,
                             int* __restrict__ partials, int n) {
    __shared__ int sh[1024];
    int i = blockIdx.x * 1024 + threadIdx.x;
    int c = (i < n) ? counts[i] : 0;
    sh[threadIdx.x] = c;
    __syncthreads();
    for (int off = 1; off < 1024; off <<= 1) {
        int t = (threadIdx.x >= off) ? sh[threadIdx.x - off] : 0;
        __syncthreads();
        sh[threadIdx.x] += t;
        __syncthreads();
    }
    if (i < n) offsets[i] = sh[threadIdx.x] - c;   // exclusive within block
    if (threadIdx.x == 1023) partials[blockIdx.x] = sh[1023];
}

__global__ void scan2_kernel(int* __restrict__ partials, int nb) {
    if (blockIdx.x == 0 && threadIdx.x == 0) {
        int run = 0;
        for (int i = 0; i < nb; i++) { int v = partials[i]; partials[i] = run; run += v; }
    }
}

__global__ void scan3_kernel(int* __restrict__ offsets,
                             const int* __restrict__ partials,
                             int* __restrict__ cursor, int n) {
    int i = blockIdx.x * blockDim.x + threadIdx.x;
    if (i < n) {
        int o = offsets[i] + partials[i >> 10];
        offsets[i] = o;
        cursor[i] = o;
    }
}

__global__ void fill_kernel(const void* __restrict__ ei_raw,
                            int* __restrict__ cursor,
                            int* __restrict__ sorted_src, int E, int n) {
    int e = blockIdx.x * blockDim.x + threadIdx.x;
    if (e >= E) return;
    int s, d; load_edge(ei_raw, E, e, s, d);
    if ((unsigned)s >= (unsigned)n || (unsigned)d >= (unsigned)n) return;
    int pos = atomicAdd(&cursor[d], 1);
    if (pos < EDGES_CAP) sorted_src[pos] = s;
}

// ---------------------------------------------------------------------------
// Fallback (shapes beyond caps): atomic scatter into g_agg
// ---------------------------------------------------------------------------
__global__ void init_agg_kernel(const float4* __restrict__ x, float4* __restrict__ agg,
                                int n4) {
    int i = blockIdx.x * blockDim.x + threadIdx.x;
    if (i < n4) agg[i] = x[i];
}

__device__ __forceinline__ void red_add_v4(float* p, float4 v) {
    asm volatile("red.global.add.v4.f32 [%0], {%1, %2, %3, %4};"
                 :: "l"(p), "f"(v.x), "f"(v.y), "f"(v.z), "f"(v.w)
                 : "memory");
}

__global__ void scatter_kernel(const float* __restrict__ x,
                               const void* __restrict__ ei_raw,
                               float* __restrict__ agg, int E, int n) {
    int t = blockIdx.x * blockDim.x + threadIdx.x;
    int e = t >> 2;
    if (e >= E) return;
    int sub = t & 3;
    int s, d; load_edge(ei_raw, E, e, s, d);
    if ((unsigned)s >= (unsigned)n || (unsigned)d >= (unsigned)n) return;
    const float4* src = (const float4*)(x + (size_t)s * CH + sub * 16);
    float*        dst = agg + (size_t)d * CH + sub * 16;
    float4 v0 = src[0], v1 = src[1], v2 = src[2], v3 = src[3];
    red_add_v4(dst + 0,  v0);
    red_add_v4(dst + 4,  v1);
    red_add_v4(dst + 8,  v2);
    red_add_v4(dst + 12, v3);
}

// ---------------------------------------------------------------------------
// Fused gather + MLP. Block = 128 threads, 128 nodes.
// Gather: warp w owns nodes w*32..w*32+31 of the block; lane holds 2 channels
// (float2). Per edge: broadcast LDG of src id + one coalesced 256B row read.
// Accumulates in registers (self row folded in), writes the smem h-tile
// directly — no agg buffer, no atomics.
// MLP: thread (tx,ty) computes rows {tx,tx+32,tx+64,tx+96} x cols [16ty,16ty+16).
// ---------------------------------------------------------------------------
#define MLP_ROWS 128
#define HP 65

__global__ void __launch_bounds__(128)
mlp_kernel(const float* __restrict__ x,
           const float* __restrict__ h_in,          // fallback: g_agg
           const int* __restrict__ offs, const int* __restrict__ cnts,
           const int* __restrict__ srt,
           const float* __restrict__ W1, const float* __restrict__ b1,
           const float* __restrict__ W2, const float* __restrict__ b2,
           const float* __restrict__ alpha,
           float* __restrict__ out, int n, int out_size, int use_gather) {
    extern __shared__ float sm[];
    float* W1s = sm;
    float* W2s = W1s + CH * CH;
    float* b1s = W2s + CH * CH;
    float* b2s = b1s + CH;
    float* hs  = b2s + CH;            // [128][65]

    const int tid = threadIdx.x;
    const int tx  = tid & 31;
    const int ty  = tid >> 5;
    const int c0  = ty * 16;
    const int row0 = blockIdx.x * MLP_ROWS;

    for (int i = tid; i < CH * CH; i += 128) { W1s[i] = W1[i]; W2s[i] = W2[i]; }
    if (tid < CH) { b1s[tid] = b1[tid]; b2s[tid] = b2[tid]; }

    if (use_gather) {
        const float2* xp = (const float2*)x;
        const int lane = tx, warp = ty;
        for (int it = 0; it < 32; it++) {
            int nb = warp * 32 + it;
            int g  = row0 + nb;
            float2 a0 = make_float2(0.f, 0.f), a1 = make_float2(0.f, 0.f);
            if (g < n) {
                a0 = xp[(size_t)g * 32 + lane];           // self (eps=0 GIN)
                int start = offs[g];
                int deg   = cnts[g];
                int j = 0;
                for (; j + 2 <= deg; j += 2) {
                    int s0 = srt[start + j];
                    int s1 = srt[start + j + 1];
                    float2 v0 = xp[(size_t)s0 * 32 + lane];
                    float2 v1 = xp[(size_t)s1 * 32 + lane];
                    a0.x += v0.x; a0.y += v0.y;
                    a1.x += v1.x; a1.y += v1.y;
                }
                if (j < deg) {
                    int s0 = srt[start + j];
                    float2 v0 = xp[(size_t)s0 * 32 + lane];
                    a0.x += v0.x; a0.y += v0.y;
                }
            }
            hs[nb * HP + 2 * lane]     = a0.x + a1.x;
            hs[nb * HP + 2 * lane + 1] = a0.y + a1.y;
        }
    } else {
        const float4* src = (const float4*)(h_in + (size_t)row0 * CH);
        int valid4 = (n - row0 < MLP_ROWS ? (n - row0 > 0 ? n - row0 : 0) : MLP_ROWS) * (CH / 4);
        for (int i = tid; i < MLP_ROWS * (CH / 4); i += 128) {
            float4 v = (i < valid4) ? src[i] : make_float4(0.f, 0.f, 0.f, 0.f);
            int r = i >> 4, q = (i & 15) * 4;
            float* dp = hs + r * HP + q;
            dp[0] = v.x; dp[1] = v.y; dp[2] = v.z; dp[3] = v.w;
        }
    }
    __syncthreads();

    const float gate = 1.0f / (1.0f + __expf(-alpha[0]));

    float acc[4][16];

    // ---- Layer 1: relu(h @ W1 + b1) ----
    #pragma unroll
    for (int j = 0; j < 4; j++)
        #pragma unroll
        for (int c = 0; c < 16; c++) acc[j][c] = b1s[c0 + c];

    #pragma unroll 4
    for (int k = 0; k < CH; k++) {
        float hv0 = hs[(tx +  0) * HP + k];
        float hv1 = hs[(tx + 32) * HP + k];
        float hv2 = hs[(tx + 64) * HP + k];
        float hv3 = hs[(tx + 96) * HP + k];
        const float4* wr = (const float4*)(W1s + k * CH + c0);
        float4 wa = wr[0], wb = wr[1], wc = wr[2], wd = wr[3];
        float w[16] = {wa.x, wa.y, wa.z, wa.w, wb.x, wb.y, wb.z, wb.w,
                       wc.x, wc.y, wc.z, wc.w, wd.x, wd.y, wd.z, wd.w};
        #pragma unroll
        for (int c = 0; c < 16; c++) {
            acc[0][c] += hv0 * w[c];
            acc[1][c] += hv1 * w[c];
            acc[2][c] += hv2 * w[c];
            acc[3][c] += hv3 * w[c];
        }
    }
    __syncthreads();
    #pragma unroll
    for (int j = 0; j < 4; j++)
        #pragma unroll
        for (int c = 0; c < 16; c++)
            hs[(32 * j + tx) * HP + c0 + c] = fmaxf(acc[j][c], 0.f);
    __syncthreads();

    // ---- Layer 2: gate * (h1 @ W2 + b2) ----
    #pragma unroll
    for (int j = 0; j < 4; j++)
        #pragma unroll
        for (int c = 0; c < 16; c++) acc[j][c] = b2s[c0 + c];

    #pragma unroll 4
    for (int k = 0; k < CH; k++) {
        float hv0 = hs[(tx +  0) * HP + k];
        float hv1 = hs[(tx + 32) * HP + k];
        float hv2 = hs[(tx + 64) * HP + k];
        float hv3 = hs[(tx + 96) * HP + k];
        const float4* wr = (const float4*)(W2s + k * CH + c0);
        float4 wa = wr[0], wb = wr[1], wc = wr[2], wd = wr[3];
        float w[16] = {wa.x, wa.y, wa.z, wa.w, wb.x, wb.y, wb.z, wb.w,
                       wc.x, wc.y, wc.z, wc.w, wd.x, wd.y, wd.z, wd.w};
        #pragma unroll
        for (int c = 0; c < 16; c++) {
            acc[0][c] += hv0 * w[c];
            acc[1][c] += hv1 * w[c];
            acc[2][c] += hv2 * w[c];
            acc[3][c] += hv3 * w[c];
        }
    }
    __syncthreads();
    #pragma unroll
    for (int j = 0; j < 4; j++)
        #pragma unroll
        for (int c = 0; c < 16; c++)
            hs[(32 * j + tx) * HP + c0 + c] = gate * acc[j][c];
    __syncthreads();

    {
        int validf = (n - row0 < MLP_ROWS ? (n - row0 > 0 ? n - row0 : 0) : MLP_ROWS) * CH;
        float* dst = out + (size_t)row0 * CH;
        for (int i = tid; i < MLP_ROWS * CH; i += 128) {
            if (i < validf) {
                int r = i >> 6, c = i & 63;
                dst[i] = hs[r * HP + c];
            }
        }
    }

    if (blockIdx.x == 0 && tid == 0 && out_size > n * CH) out[(size_t)n * CH] = gate;
}

// ---------------------------------------------------------------------------
extern "C" void kernel_launch(void* const* d_in, const int* in_sizes, int n_in,
                              void* d_out, int out_size) {
    const float* x     = (const float*)d_in[0];
    const void*  ei    = d_in[1];
    const float* W1    = (const float*)d_in[2];
    const float* b1    = (const float*)d_in[3];
    const float* W2    = (const float*)d_in[4];
    const float* b2    = (const float*)d_in[5];
    const float* alpha = (const float*)d_in[6];
    float* out = (float*)d_out;

    int n = in_sizes[0] / CH;
    int E = in_sizes[1] / 2;

    float *agg; int *counts, *offsets, *cursor, *sorted, *partials;
    cudaGetSymbolAddress((void**)&agg,      g_agg);
    cudaGetSymbolAddress((void**)&counts,   g_counts);
    cudaGetSymbolAddress((void**)&offsets,  g_offsets);
    cudaGetSymbolAddress((void**)&cursor,   g_cursor);
    cudaGetSymbolAddress((void**)&sorted,   g_sorted_src);
    cudaGetSymbolAddress((void**)&partials, g_partials);

    probe_ei_kernel<<<1, 1>>>((const int*)ei);

    int smem = (2 * CH * CH + 2 * CH + MLP_ROWS * HP) * sizeof(float);
    cudaFuncSetAttribute(mlp_kernel, cudaFuncAttributeMaxDynamicSharedMemorySize, smem);
    int mblocks = (n + MLP_ROWS - 1) / MLP_ROWS;

    bool sortable = (n <= NODES_CAP) && (E <= EDGES_CAP) && (((n + 1023) / 1024) <= 256);

    if (sortable) {
        int nb = (n + 1023) / 1024;
        zero_counts_kernel<<<(n + 255) / 256, 256>>>(counts, n);
        hist_kernel<<<(E + 255) / 256, 256>>>(ei, counts, E, n);
        scan1_kernel<<<nb, 1024>>>(counts, offsets, partials, n);
        scan2_kernel<<<1, 32>>>(partials, nb);
        scan3_kernel<<<(n + 255) / 256, 256>>>(offsets, partials, cursor, n);
        fill_kernel<<<(E + 255) / 256, 256>>>(ei, cursor, sorted, E, n);
        mlp_kernel<<<mblocks, 128, smem>>>(x, x, offsets, counts, sorted,
                                           W1, b1, W2, b2, alpha, out, n, out_size, 1);
    } else {
        int ncap = n < NODES_CAP ? n : NODES_CAP;
        int n4 = ncap * (CH / 4);
        init_agg_kernel<<<(n4 + 255) / 256, 256>>>((const float4*)x, (float4*)agg, n4);
        long long thr = (long long)E * 4;
        scatter_kernel<<<(int)((thr + 255) / 256), 256>>>(x, ei, agg, E, ncap);
        mlp_kernel<<<(ncap + MLP_ROWS - 1) / MLP_ROWS, 128, smem>>>(
            x, agg, offsets, counts, sorted,
            W1, b1, W2, b2, alpha, out, ncap, out_size, 0);
    }
}